// round 15
// baseline (speedup 1.0000x reference)
#include <cuda_runtime.h>
#include <cuda_fp16.h>
#include <mma.h>

using namespace nvcuda;

// Problem constants (fixed by the dataset)
#define N_NODES 50000
#define N_EDGES 1600000
#define D 128

// ---------------- scratch (device globals; no allocation allowed) ----------
__device__ __align__(16) __half g_x16[N_NODES * D];  // fp16 GEMM input
__device__ __align__(16) __half g_z16[N_NODES * D];  // fp16 GEMM output / gather payload
__device__ __align__(16) __half g_w16[3 * D * D];    // fp16 weights
__device__ float g_asrc[N_NODES];
__device__ float g_adst[N_NODES];
__device__ int   g_deg[N_NODES];
__device__ int   g_cur[N_NODES];
__device__ int   g_off[N_NODES + 1];
__device__ int   g_bsum[64];            // per-block sums for the 3-phase scan
__device__ int   g_bhist[256];          // degree-bin histogram (descending bins)
__device__ int   g_bcur[256];           // degree-bin cursors
__device__ int   g_perm[N_NODES];       // nodes sorted by descending degree
__device__ int   g_csr_src[N_EDGES];

// ---------------- CSR build ------------------------------------------------
__global__ void zero_kernel(int* a, int* b, int* bh, int n) {
    int i = blockIdx.x * blockDim.x + threadIdx.x;
    if (i < n) { a[i] = 0; b[i] = 0; }
    if (i < 256) bh[i] = 0;
}

__global__ void hist_kernel(const int* __restrict__ dst, int* __restrict__ deg, int E) {
    int i4 = (blockIdx.x * blockDim.x + threadIdx.x) * 4;
    if (i4 + 3 < E) {
        int4 v = *(const int4*)(dst + i4);
        atomicAdd(&deg[v.x], 1);
        atomicAdd(&deg[v.y], 1);
        atomicAdd(&deg[v.z], 1);
        atomicAdd(&deg[v.w], 1);
    } else {
        for (int i = i4; i < E; i++) atomicAdd(&deg[dst[i]], 1);
    }
}

// ---- 3-phase coalesced exclusive scan (1024 elems per block) ----
#define SCAN_TPB 1024

// phase A: per-block reduce (coalesced)
__global__ void scan_bsum_kernel(const int* __restrict__ deg, int* __restrict__ bsum,
                                 int n) {
    __shared__ int wsum[32];
    int lane = threadIdx.x & 31, wid = threadIdx.x >> 5;
    int i = blockIdx.x * SCAN_TPB + threadIdx.x;
    int x = (i < n) ? deg[i] : 0;
#pragma unroll
    for (int o = 16; o; o >>= 1) x += __shfl_xor_sync(0xffffffffu, x, o);
    if (lane == 0) wsum[wid] = x;
    __syncthreads();
    if (wid == 0) {
        int w = wsum[lane];
#pragma unroll
        for (int o = 16; o; o >>= 1) w += __shfl_xor_sync(0xffffffffu, w, o);
        if (lane == 0) bsum[blockIdx.x] = w;
    }
}

// phase B: parallel exclusive scan of block sums (nb <= 64) with 64 threads;
// writes off[n]=total
__global__ void scan_bpre_kernel(int* __restrict__ bsum, int* __restrict__ off,
                                 int nb, int n) {
    __shared__ int w0sum;
    int tid = threadIdx.x;          // 0..63
    int lane = tid & 31, wid = tid >> 5;
    int v = (tid < nb) ? bsum[tid] : 0;
    int x = v;
#pragma unroll
    for (int o = 1; o < 32; o <<= 1) {
        int y = __shfl_up_sync(0xffffffffu, x, o);
        if (lane >= o) x += y;
    }
    if (wid == 0 && lane == 31) w0sum = x;
    __syncthreads();
    int excl = x - v + (wid ? w0sum : 0);
    if (tid < nb) bsum[tid] = excl;
    if (tid == nb - 1) off[n] = excl + v;
}

// phase C: per-block exclusive scan + block prefix, coalesced off store
__global__ void scan_write_kernel(const int* __restrict__ deg, const int* __restrict__ bsum,
                                  int* __restrict__ off, int n) {
    __shared__ int wsum[32];
    int lane = threadIdx.x & 31, wid = threadIdx.x >> 5;
    int i = blockIdx.x * SCAN_TPB + threadIdx.x;
    int v = (i < n) ? deg[i] : 0;
    int x = v;
#pragma unroll
    for (int o = 1; o < 32; o <<= 1) {
        int y = __shfl_up_sync(0xffffffffu, x, o);
        if (lane >= o) x += y;
    }
    if (lane == 31) wsum[wid] = x;
    __syncthreads();
    if (wid == 0) {
        int w = wsum[lane];
#pragma unroll
        for (int o = 1; o < 32; o <<= 1) {
            int y = __shfl_up_sync(0xffffffffu, w, o);
            if (lane >= o) w += y;
        }
        wsum[lane] = w;
    }
    __syncthreads();
    int excl = x - v + (wid ? wsum[wid - 1] : 0) + bsum[blockIdx.x];
    if (i < n) off[i] = excl;
}

__global__ void scatter_kernel(const int* __restrict__ src, const int* __restrict__ dst,
                               const int* __restrict__ off, int* __restrict__ cur,
                               int* __restrict__ csr_src, int E) {
    int i = blockIdx.x * blockDim.x + threadIdx.x;
    if (i >= E) return;
    int d = dst[i];
    int p = off[d] + atomicAdd(&cur[d], 1);
    csr_src[p] = src[i];
}

// ---- degree-descending counting sort of nodes (for aggregate scheduling) ----
__global__ void bin_hist_kernel(const int* __restrict__ deg, int* __restrict__ bhist,
                                int n) {
    int i = blockIdx.x * blockDim.x + threadIdx.x;
    if (i >= n) return;
    int b = 255 - min(deg[i], 255);   // descending degree order
    atomicAdd(&bhist[b], 1);
}

// 256-bin exclusive prefix (1 block, 256 threads); writes prefix into both
// bhist (for reference) and bcur (working cursors)
__global__ void bin_prefix_kernel(int* __restrict__ bhist, int* __restrict__ bcur) {
    __shared__ int wsum[8];
    int tid = threadIdx.x;            // 0..255
    int lane = tid & 31, wid = tid >> 5;
    int v = bhist[tid];
    int x = v;
#pragma unroll
    for (int o = 1; o < 32; o <<= 1) {
        int y = __shfl_up_sync(0xffffffffu, x, o);
        if (lane >= o) x += y;
    }
    if (lane == 31) wsum[wid] = x;
    __syncthreads();
    if (wid == 0 && lane < 8) {
        int w = wsum[lane];
#pragma unroll
        for (int o = 1; o < 8; o <<= 1) {
            int y = __shfl_up_sync(0x000000ffu, w, o);
            if (lane >= o) w += y;
        }
        wsum[lane] = w;
    }
    __syncthreads();
    int excl = x - v + (wid ? wsum[wid - 1] : 0);
    bhist[tid] = excl;
    bcur[tid] = excl;
}

__global__ void perm_scatter_kernel(const int* __restrict__ deg, int* __restrict__ bcur,
                                    int* __restrict__ perm, int n) {
    int i = blockIdx.x * blockDim.x + threadIdx.x;
    if (i >= n) return;
    int b = 255 - min(deg[i], 255);
    int pos = atomicAdd(&bcur[b], 1);
    perm[pos] = i;
}

// ---------------- fp32 -> fp16 conversions ----------------------------------
__global__ void cvt_x_kernel(const float* __restrict__ in, __half* __restrict__ out16,
                             int n8) {
    int i = blockIdx.x * blockDim.x + threadIdx.x;
    if (i >= n8) return;
    const float4* p = (const float4*)in + (size_t)i * 2;
    float4 a = p[0], b = p[1];
    __half2 h0 = __floats2half2_rn(a.x, a.y);
    __half2 h1 = __floats2half2_rn(a.z, a.w);
    __half2 h2 = __floats2half2_rn(b.x, b.y);
    __half2 h3 = __floats2half2_rn(b.z, b.w);
    uint4 u;
    u.x = *reinterpret_cast<unsigned*>(&h0);
    u.y = *reinterpret_cast<unsigned*>(&h1);
    u.z = *reinterpret_cast<unsigned*>(&h2);
    u.w = *reinterpret_cast<unsigned*>(&h3);
    *((uint4*)out16 + i) = u;
}

__global__ void cvt_w_kernel(const float* __restrict__ W0, const float* __restrict__ W1,
                             const float* __restrict__ W2, __half* __restrict__ w16) {
    int i = blockIdx.x * blockDim.x + threadIdx.x;  // 3 * 2048 vec8 chunks
    if (i >= 3 * 2048) return;
    int which = i >> 11, j = i & 2047;
    const float* W = (which == 0) ? W0 : ((which == 1) ? W1 : W2);
    const float4* p = (const float4*)W + (size_t)j * 2;
    float4 a = p[0], b = p[1];
    __half2 h0 = __floats2half2_rn(a.x, a.y);
    __half2 h1 = __floats2half2_rn(a.z, a.w);
    __half2 h2 = __floats2half2_rn(b.x, b.y);
    __half2 h3 = __floats2half2_rn(b.z, b.w);
    uint4 u;
    u.x = *reinterpret_cast<unsigned*>(&h0);
    u.y = *reinterpret_cast<unsigned*>(&h1);
    u.z = *reinterpret_cast<unsigned*>(&h2);
    u.w = *reinterpret_cast<unsigned*>(&h3);
    *((uint4*)(w16 + (size_t)which * D * D) + j) = u;
}

// ---------------- WMMA GEMM + fused attention projections -------------------
// Z16 = fp16(X16 @ W16^T + b); asrc/adst = Z @ aW halves from fp32 accums.
// Block: 128 rows, full N=128, full K=128 staged once. 8 warps, 16 rows each,
// 8 accumulator fragments per warp. Padded ld=136 halves for staging tiles.
// W is [n][k] row-major; as a col_major wmma matrix_b this gives
// B(k,n) = W[n][k] exactly.
#define LDP 136
#define GEMM_SMEM_BYTES (2 * 128 * LDP * 2)   // 69632; also covers 128*128*4 float C

__global__ __launch_bounds__(256) void gemm_kernel(
    const __half* __restrict__ X16, const __half* __restrict__ W16,
    const float* __restrict__ bias, const float* __restrict__ aW,
    __half* __restrict__ Z16, float* __restrict__ asrc, float* __restrict__ adst, int n)
{
    extern __shared__ __half smbuf[];
    __half* As = smbuf;                  // [128][LDP]
    __half* Ws = smbuf + 128 * LDP;      // [128][LDP]
    int tid = threadIdx.x;
    int row0 = blockIdx.x * 128;

    // stage X tile (zero-filled past n) and W, 8 x 16B chunks per thread each
    for (int i = 0; i < 8; i++) {
        int c = tid + i * 256;           // 0..2047
        int row = c >> 4;
        int k8 = c & 15;
        uint4 v = make_uint4(0u, 0u, 0u, 0u);
        int grow = row0 + row;
        if (grow < n) v = *(const uint4*)(X16 + (size_t)grow * D + k8 * 8);
        *(uint4*)(As + row * LDP + k8 * 8) = v;
        uint4 wv = *(const uint4*)(W16 + row * D + k8 * 8);
        *(uint4*)(Ws + row * LDP + k8 * 8) = wv;
    }
    __syncthreads();

    int warp = tid >> 5;
    wmma::fragment<wmma::accumulator, 16, 16, 16, float> cfrag[8];
    for (int j = 0; j < 8; j++) wmma::fill_fragment(cfrag[j], 0.0f);

    for (int k = 0; k < 8; k++) {
        wmma::fragment<wmma::matrix_a, 16, 16, 16, __half, wmma::row_major> afrag;
        wmma::load_matrix_sync(afrag, As + (warp * 16) * LDP + k * 16, LDP);
        for (int j = 0; j < 8; j++) {
            wmma::fragment<wmma::matrix_b, 16, 16, 16, __half, wmma::col_major> bfrag;
            wmma::load_matrix_sync(bfrag, Ws + (j * 16) * LDP + k * 16, LDP);
            wmma::mma_sync(cfrag[j], afrag, bfrag, cfrag[j]);
        }
    }
    __syncthreads();   // tiles dead; reuse smem for the fp32 C buffer

    float* Cs = (float*)smbuf;           // [128][128]
    for (int j = 0; j < 8; j++)
        wmma::store_matrix_sync(Cs + (warp * 16) * 128 + j * 16, cfrag[j], 128,
                                wmma::mem_row_major);
    __syncthreads();

    // epilogue: thread t handles row t/2, 64 channels; pair-reduce projections
    int row = tid >> 1;
    int hh = tid & 1;
    int c0 = hh * 64;
    int grow = row0 + row;
    float p1 = 0.f, p2 = 0.f;
    __half2 hv[32];
    for (int j = 0; j < 32; j++) {
        float ox = Cs[row * 128 + c0 + 2 * j]     + bias[c0 + 2 * j];
        float oy = Cs[row * 128 + c0 + 2 * j + 1] + bias[c0 + 2 * j + 1];
        p1 += ox * aW[c0 + 2 * j]     + oy * aW[c0 + 2 * j + 1];
        p2 += ox * aW[D + c0 + 2 * j] + oy * aW[D + c0 + 2 * j + 1];
        hv[j] = __floats2half2_rn(ox, oy);
    }
    p1 += __shfl_xor_sync(0xffffffffu, p1, 1);
    p2 += __shfl_xor_sync(0xffffffffu, p2, 1);
    if (grow < n) {
        uint4* dst4 = (uint4*)(Z16 + (size_t)grow * D + c0);
        const uint4* src4 = (const uint4*)hv;
        for (int j = 0; j < 8; j++) dst4[j] = src4[j];
        if (hh == 0) { asrc[grow] = p1; adst[grow] = p2; }
    }
}

// ---------------- fused segment softmax + weighted gather ------------------
// One warp per dst node, nodes visited in descending-degree order via perm
// (bit-identical results; scheduling only). Fast path (deg <= 128): pass 1
// stages (e, src) per edge into per-warp smem; pass 2a converts e -> alpha in
// place; pass 2b reads alpha/src from smem and issues independent LDG.128
// row loads, 2 edges per step, 16 lanes x 16B per row. Slow path recomputes.
// outh != 0: write relu'd fp16; else fp32 to outf.
#define AGG_CAP 128

__global__ __launch_bounds__(256) void aggregate_kernel(
    const __half* __restrict__ z16,
    const float* __restrict__ asrc,
    const float* __restrict__ adst,
    const int* __restrict__ off,
    const int* __restrict__ csr_src,
    const int* __restrict__ perm,
    const float* __restrict__ ab,
    float* __restrict__ outf,
    __half* __restrict__ outh, int n)
{
    __shared__ float s_alpha[8][AGG_CAP + 2];
    __shared__ int   s_sj[8][AGG_CAP + 2];

    int slot = (blockIdx.x * blockDim.x + threadIdx.x) >> 5;
    int lane = threadIdx.x & 31;
    int w = (threadIdx.x >> 5);
    if (slot >= n) return;
    int node = perm[slot];
    int beg = off[node], end = off[node + 1];
    int deg = end - beg;
    float advv = adst[node] + ab[0];

    int hf = lane >> 4;
    int chan = (lane & 15) * 8;
    float acc8[8] = {0.f, 0.f, 0.f, 0.f, 0.f, 0.f, 0.f, 0.f};
    float m = -1e30f, s = 0.f;

    if (deg <= AGG_CAP) {
        // ---- pass 1: gather e/src, stage to smem, online stats ----
        for (int idx = lane; idx < deg; idx += 32) {
            int sj = csr_src[beg + idx];
            float e = asrc[sj] + advv;
            e = (e > 0.f) ? e : 0.01f * e;
            s_alpha[w][idx] = e;
            s_sj[w][idx] = sj;
            if (e > m) { s = s * __expf(m - e) + 1.f; m = e; }
            else       { s += __expf(e - m); }
        }
#pragma unroll
        for (int o = 16; o; o >>= 1) {
            float m2 = __shfl_xor_sync(0xffffffffu, m, o);
            float s2 = __shfl_xor_sync(0xffffffffu, s, o);
            float mn = fmaxf(m, m2);
            s = s * __expf(m - mn) + s2 * __expf(m2 - mn);
            m = mn;
        }
        float inv_s = (deg > 0) ? 1.f / s : 0.f;
        // ---- pass 2a: e -> alpha in smem; pad one slot ----
        for (int idx = lane; idx < deg; idx += 32) {
            s_alpha[w][idx] = __expf(s_alpha[w][idx] - m) * inv_s;
        }
        if (lane == 0) { s_alpha[w][deg] = 0.f; s_sj[w][deg] = 0; }
        __syncwarp();
        // ---- pass 2b: weighted gather, 2 edges/step ----
        int steps = (deg + 1) >> 1;
#pragma unroll 8
        for (int t = 0; t < steps; t++) {
            int idx = 2 * t + hf;
            float a  = s_alpha[w][idx];
            int   sn = s_sj[w][idx];
            uint4 raw = *(const uint4*)(z16 + (size_t)sn * D + chan);
            __half2 q0 = *reinterpret_cast<__half2*>(&raw.x);
            __half2 q1 = *reinterpret_cast<__half2*>(&raw.y);
            __half2 q2 = *reinterpret_cast<__half2*>(&raw.z);
            __half2 q3 = *reinterpret_cast<__half2*>(&raw.w);
            float2 f0 = __half22float2(q0);
            float2 f1 = __half22float2(q1);
            float2 f2 = __half22float2(q2);
            float2 f3 = __half22float2(q3);
            acc8[0] += a * f0.x;
            acc8[1] += a * f0.y;
            acc8[2] += a * f1.x;
            acc8[3] += a * f1.y;
            acc8[4] += a * f2.x;
            acc8[5] += a * f2.y;
            acc8[6] += a * f3.x;
            acc8[7] += a * f3.y;
        }
    } else {
        // ---- slow path (deg > 128): recompute ----
        for (int j = beg + lane; j < end; j += 32) {
            float e = asrc[csr_src[j]] + advv;
            e = (e > 0.f) ? e : 0.01f * e;
            if (e > m) { s = s * __expf(m - e) + 1.f; m = e; }
            else       { s += __expf(e - m); }
        }
#pragma unroll
        for (int o = 16; o; o >>= 1) {
            float m2 = __shfl_xor_sync(0xffffffffu, m, o);
            float s2 = __shfl_xor_sync(0xffffffffu, s, o);
            float mn = fmaxf(m, m2);
            s = s * __expf(m - mn) + s2 * __expf(m2 - mn);
            m = mn;
        }
        float inv_s = 1.f / s;
        for (int j0 = beg; j0 < end; j0 += 32) {
            int j = j0 + lane;
            float alpha = 0.f;
            int sj = 0;
            if (j < end) {
                sj = csr_src[j];
                float e = asrc[sj] + advv;
                e = (e > 0.f) ? e : 0.01f * e;
                alpha = __expf(e - m) * inv_s;
            }
            int cnt = min(32, end - j0);
            int steps = (cnt + 1) >> 1;
            for (int t = 0; t < steps; t++) {
                float a  = __shfl_sync(0xffffffffu, alpha, 2 * t + hf);
                int   sn = __shfl_sync(0xffffffffu, sj,    2 * t + hf);
                uint4 raw = *(const uint4*)(z16 + (size_t)sn * D + chan);
                __half2 q0 = *reinterpret_cast<__half2*>(&raw.x);
                __half2 q1 = *reinterpret_cast<__half2*>(&raw.y);
                __half2 q2 = *reinterpret_cast<__half2*>(&raw.z);
                __half2 q3 = *reinterpret_cast<__half2*>(&raw.w);
                float2 f0 = __half22float2(q0);
                float2 f1 = __half22float2(q1);
                float2 f2 = __half22float2(q2);
                float2 f3 = __half22float2(q3);
                acc8[0] += a * f0.x;
                acc8[1] += a * f0.y;
                acc8[2] += a * f1.x;
                acc8[3] += a * f1.y;
                acc8[4] += a * f2.x;
                acc8[5] += a * f2.y;
                acc8[6] += a * f3.x;
                acc8[7] += a * f3.y;
            }
        }
    }

    // combine the two edge-halves
#pragma unroll
    for (int c = 0; c < 8; c++) {
        acc8[c] += __shfl_xor_sync(0xffffffffu, acc8[c], 16);
    }

    if (lane < 16) {
        if (outh != 0) {
            __half2 h0 = __floats2half2_rn(fmaxf(acc8[0], 0.f), fmaxf(acc8[1], 0.f));
            __half2 h1 = __floats2half2_rn(fmaxf(acc8[2], 0.f), fmaxf(acc8[3], 0.f));
            __half2 h2 = __floats2half2_rn(fmaxf(acc8[4], 0.f), fmaxf(acc8[5], 0.f));
            __half2 h3 = __floats2half2_rn(fmaxf(acc8[6], 0.f), fmaxf(acc8[7], 0.f));
            uint4 u;
            u.x = *reinterpret_cast<unsigned*>(&h0);
            u.y = *reinterpret_cast<unsigned*>(&h1);
            u.z = *reinterpret_cast<unsigned*>(&h2);
            u.w = *reinterpret_cast<unsigned*>(&h3);
            *(uint4*)(outh + (size_t)node * D + chan) = u;
        } else {
            *(float4*)(outf + (size_t)node * D + chan) =
                make_float4(acc8[0], acc8[1], acc8[2], acc8[3]);
            *(float4*)(outf + (size_t)node * D + chan + 4) =
                make_float4(acc8[4], acc8[5], acc8[6], acc8[7]);
        }
    }
}

// ---------------- launch ----------------------------------------------------
extern "C" void kernel_launch(void* const* d_in, const int* in_sizes, int n_in,
                              void* d_out, int out_size)
{
    const float* x   = (const float*)d_in[0];
    const int*   src = (const int*)d_in[1];
    const int*   dst = (const int*)d_in[2];
    // d_in[3] = t (unused)
    const float* W0  = (const float*)d_in[4];
    const float* b0  = (const float*)d_in[5];
    const float* aW0 = (const float*)d_in[6];
    const float* ab0 = (const float*)d_in[7];
    const float* W1  = (const float*)d_in[8];
    const float* b1  = (const float*)d_in[9];
    const float* aW1 = (const float*)d_in[10];
    const float* ab1 = (const float*)d_in[11];
    const float* W2  = (const float*)d_in[12];
    const float* b2  = (const float*)d_in[13];
    const float* aW2 = (const float*)d_in[14];
    const float* ab2 = (const float*)d_in[15];

    int n = in_sizes[0] / D;   // 50000
    int E = in_sizes[1];       // 1600000

    __half *x16, *z16, *w16;
    float *asrc, *adst;
    int *deg, *cur, *off, *csr, *bsum, *bhist, *bcur, *perm;
    cudaGetSymbolAddress((void**)&x16,   g_x16);
    cudaGetSymbolAddress((void**)&z16,   g_z16);
    cudaGetSymbolAddress((void**)&w16,   g_w16);
    cudaGetSymbolAddress((void**)&asrc,  g_asrc);
    cudaGetSymbolAddress((void**)&adst,  g_adst);
    cudaGetSymbolAddress((void**)&deg,   g_deg);
    cudaGetSymbolAddress((void**)&cur,   g_cur);
    cudaGetSymbolAddress((void**)&off,   g_off);
    cudaGetSymbolAddress((void**)&bsum,  g_bsum);
    cudaGetSymbolAddress((void**)&bhist, g_bhist);
    cudaGetSymbolAddress((void**)&bcur,  g_bcur);
    cudaGetSymbolAddress((void**)&perm,  g_perm);
    cudaGetSymbolAddress((void**)&csr,   g_csr_src);

    float* outf = (float*)d_out;

    // idempotent, host-side, not a stream op (safe under graph capture)
    cudaFuncSetAttribute(gemm_kernel, cudaFuncAttributeMaxDynamicSharedMemorySize,
                         GEMM_SMEM_BYTES);

    int tb = 256;
    int scan_blocks = (n + SCAN_TPB - 1) / SCAN_TPB;   // 49
    // ---- CSR build ----
    zero_kernel<<<(n + tb - 1) / tb, tb>>>(deg, cur, bhist, n);
    hist_kernel<<<(E / 4 + tb - 1) / tb, tb>>>(dst, deg, E);
    scan_bsum_kernel<<<scan_blocks, SCAN_TPB>>>(deg, bsum, n);
    scan_bpre_kernel<<<1, 64>>>(bsum, off, scan_blocks, n);
    scan_write_kernel<<<scan_blocks, SCAN_TPB>>>(deg, bsum, off, n);
    scatter_kernel<<<(E + tb - 1) / tb, tb>>>(src, dst, off, cur, csr, E);

    // ---- degree-descending node permutation ----
    bin_hist_kernel<<<(n + tb - 1) / tb, tb>>>(deg, bhist, n);
    bin_prefix_kernel<<<1, 256>>>(bhist, bcur);
    perm_scatter_kernel<<<(n + tb - 1) / tb, tb>>>(deg, bcur, perm, n);

    // ---- conversions: x and the three weight matrices to fp16 ----
    int n8x = n * D / 8;
    cvt_x_kernel<<<(n8x + tb - 1) / tb, tb>>>(x, x16, n8x);
    cvt_w_kernel<<<(3 * 2048 + tb - 1) / tb, tb>>>(W0, W1, W2, w16);

    int gemm_blocks = (n + 127) / 128;
    int warp_blocks = (n + 7) / 8;

    // ---- layer 0 (fp16 relu out -> x16) ----
    gemm_kernel<<<gemm_blocks, tb, GEMM_SMEM_BYTES>>>(x16, w16, b0, aW0, z16, asrc, adst, n);
    aggregate_kernel<<<warp_blocks, tb>>>(z16, asrc, adst, off, csr, perm, ab0, 0, x16, n);
    // ---- layer 1 ----
    gemm_kernel<<<gemm_blocks, tb, GEMM_SMEM_BYTES>>>(x16, w16 + D * D, b1, aW1, z16, asrc, adst, n);
    aggregate_kernel<<<warp_blocks, tb>>>(z16, asrc, adst, off, csr, perm, ab1, 0, x16, n);
    // ---- layer 2 (fp32 out -> d_out) ----
    gemm_kernel<<<gemm_blocks, tb, GEMM_SMEM_BYTES>>>(x16, w16 + 2 * D * D, b2, aW2, z16, asrc, adst, n);
    aggregate_kernel<<<warp_blocks, tb>>>(z16, asrc, adst, off, csr, perm, ab2, outf, 0, n);
}

// round 16
// speedup vs baseline: 1.0767x; 1.0767x over previous
#include <cuda_runtime.h>
#include <cuda_fp16.h>
#include <mma.h>

using namespace nvcuda;

// Problem constants (fixed by the dataset)
#define N_NODES 50000
#define N_EDGES 1600000
#define D 128

// ---------------- scratch (device globals; no allocation allowed) ----------
__device__ __align__(16) __half g_x16[N_NODES * D];  // fp16 GEMM input
__device__ __align__(16) __half g_z16[N_NODES * D];  // fp16 GEMM output / gather payload
__device__ __align__(16) __half g_w16[3 * D * D];    // fp16 weights
__device__ float g_asrc[N_NODES];
__device__ float g_adst[N_NODES];
__device__ int   g_deg[N_NODES];
__device__ int   g_cur[N_NODES];
__device__ int   g_off[N_NODES + 1];
__device__ int   g_bsum[64];            // per-block sums for the 3-phase scan
__device__ int   g_csr_src[N_EDGES];

// ---------------- CSR build ------------------------------------------------
__global__ void zero_kernel(int* a, int* b, int n) {
    int i = blockIdx.x * blockDim.x + threadIdx.x;
    if (i < n) { a[i] = 0; b[i] = 0; }
}

__global__ void hist_kernel(const int* __restrict__ dst, int* __restrict__ deg, int E) {
    int i4 = (blockIdx.x * blockDim.x + threadIdx.x) * 4;
    if (i4 + 3 < E) {
        int4 v = *(const int4*)(dst + i4);
        atomicAdd(&deg[v.x], 1);
        atomicAdd(&deg[v.y], 1);
        atomicAdd(&deg[v.z], 1);
        atomicAdd(&deg[v.w], 1);
    } else {
        for (int i = i4; i < E; i++) atomicAdd(&deg[dst[i]], 1);
    }
}

// ---- 3-phase coalesced exclusive scan (1024 elems per block) ----
#define SCAN_TPB 1024

// phase A: per-block reduce (coalesced)
__global__ void scan_bsum_kernel(const int* __restrict__ deg, int* __restrict__ bsum,
                                 int n) {
    __shared__ int wsum[32];
    int lane = threadIdx.x & 31, wid = threadIdx.x >> 5;
    int i = blockIdx.x * SCAN_TPB + threadIdx.x;
    int x = (i < n) ? deg[i] : 0;
#pragma unroll
    for (int o = 16; o; o >>= 1) x += __shfl_xor_sync(0xffffffffu, x, o);
    if (lane == 0) wsum[wid] = x;
    __syncthreads();
    if (wid == 0) {
        int w = wsum[lane];
#pragma unroll
        for (int o = 16; o; o >>= 1) w += __shfl_xor_sync(0xffffffffu, w, o);
        if (lane == 0) bsum[blockIdx.x] = w;
    }
}

// phase B: parallel exclusive scan of block sums (nb <= 64) with 64 threads;
// writes off[n]=total
__global__ void scan_bpre_kernel(int* __restrict__ bsum, int* __restrict__ off,
                                 int nb, int n) {
    __shared__ int w0sum;
    int tid = threadIdx.x;          // 0..63
    int lane = tid & 31, wid = tid >> 5;
    int v = (tid < nb) ? bsum[tid] : 0;
    int x = v;
#pragma unroll
    for (int o = 1; o < 32; o <<= 1) {
        int y = __shfl_up_sync(0xffffffffu, x, o);
        if (lane >= o) x += y;
    }
    if (wid == 0 && lane == 31) w0sum = x;
    __syncthreads();
    int excl = x - v + (wid ? w0sum : 0);
    if (tid < nb) bsum[tid] = excl;
    if (tid == nb - 1) off[n] = excl + v;
}

// phase C: per-block exclusive scan + block prefix, coalesced off store
__global__ void scan_write_kernel(const int* __restrict__ deg, const int* __restrict__ bsum,
                                  int* __restrict__ off, int n) {
    __shared__ int wsum[32];
    int lane = threadIdx.x & 31, wid = threadIdx.x >> 5;
    int i = blockIdx.x * SCAN_TPB + threadIdx.x;
    int v = (i < n) ? deg[i] : 0;
    int x = v;
#pragma unroll
    for (int o = 1; o < 32; o <<= 1) {
        int y = __shfl_up_sync(0xffffffffu, x, o);
        if (lane >= o) x += y;
    }
    if (lane == 31) wsum[wid] = x;
    __syncthreads();
    if (wid == 0) {
        int w = wsum[lane];
#pragma unroll
        for (int o = 1; o < 32; o <<= 1) {
            int y = __shfl_up_sync(0xffffffffu, w, o);
            if (lane >= o) w += y;
        }
        wsum[lane] = w;
    }
    __syncthreads();
    int excl = x - v + (wid ? wsum[wid - 1] : 0) + bsum[blockIdx.x];
    if (i < n) off[i] = excl;
}

__global__ void scatter_kernel(const int* __restrict__ src, const int* __restrict__ dst,
                               const int* __restrict__ off, int* __restrict__ cur,
                               int* __restrict__ csr_src, int E) {
    int i = blockIdx.x * blockDim.x + threadIdx.x;
    if (i >= E) return;
    int d = dst[i];
    int p = off[d] + atomicAdd(&cur[d], 1);
    csr_src[p] = src[i];
}

// ---------------- fp32 -> fp16 conversions ----------------------------------
__global__ void cvt_x_kernel(const float* __restrict__ in, __half* __restrict__ out16,
                             int n8) {
    int i = blockIdx.x * blockDim.x + threadIdx.x;
    if (i >= n8) return;
    const float4* p = (const float4*)in + (size_t)i * 2;
    float4 a = p[0], b = p[1];
    __half2 h0 = __floats2half2_rn(a.x, a.y);
    __half2 h1 = __floats2half2_rn(a.z, a.w);
    __half2 h2 = __floats2half2_rn(b.x, b.y);
    __half2 h3 = __floats2half2_rn(b.z, b.w);
    uint4 u;
    u.x = *reinterpret_cast<unsigned*>(&h0);
    u.y = *reinterpret_cast<unsigned*>(&h1);
    u.z = *reinterpret_cast<unsigned*>(&h2);
    u.w = *reinterpret_cast<unsigned*>(&h3);
    *((uint4*)out16 + i) = u;
}

__global__ void cvt_w_kernel(const float* __restrict__ W0, const float* __restrict__ W1,
                             const float* __restrict__ W2, __half* __restrict__ w16) {
    int i = blockIdx.x * blockDim.x + threadIdx.x;  // 3 * 2048 vec8 chunks
    if (i >= 3 * 2048) return;
    int which = i >> 11, j = i & 2047;
    const float* W = (which == 0) ? W0 : ((which == 1) ? W1 : W2);
    const float4* p = (const float4*)W + (size_t)j * 2;
    float4 a = p[0], b = p[1];
    __half2 h0 = __floats2half2_rn(a.x, a.y);
    __half2 h1 = __floats2half2_rn(a.z, a.w);
    __half2 h2 = __floats2half2_rn(b.x, b.y);
    __half2 h3 = __floats2half2_rn(b.z, b.w);
    uint4 u;
    u.x = *reinterpret_cast<unsigned*>(&h0);
    u.y = *reinterpret_cast<unsigned*>(&h1);
    u.z = *reinterpret_cast<unsigned*>(&h2);
    u.w = *reinterpret_cast<unsigned*>(&h3);
    *((uint4*)(w16 + (size_t)which * D * D) + j) = u;
}

// ---------------- WMMA GEMM + fused attention projections -------------------
// Z16 = fp16(X16 @ W16^T + b); asrc/adst = Z @ aW halves from fp32 accums.
// Block: 128 rows, full N=128, full K=128 staged once. 8 warps, 16 rows each,
// 8 accumulator fragments per warp. Padded ld=136 halves for staging tiles.
// W is [n][k] row-major; as a col_major wmma matrix_b this gives
// B(k,n) = W[n][k] exactly.
#define LDP 136
#define GEMM_SMEM_BYTES (2 * 128 * LDP * 2)   // 69632; also covers 128*128*4 float C

__global__ __launch_bounds__(256) void gemm_kernel(
    const __half* __restrict__ X16, const __half* __restrict__ W16,
    const float* __restrict__ bias, const float* __restrict__ aW,
    __half* __restrict__ Z16, float* __restrict__ asrc, float* __restrict__ adst, int n)
{
    extern __shared__ __half smbuf[];
    __half* As = smbuf;                  // [128][LDP]
    __half* Ws = smbuf + 128 * LDP;      // [128][LDP]
    int tid = threadIdx.x;
    int row0 = blockIdx.x * 128;

    // stage X tile (zero-filled past n) and W, 8 x 16B chunks per thread each
    for (int i = 0; i < 8; i++) {
        int c = tid + i * 256;           // 0..2047
        int row = c >> 4;
        int k8 = c & 15;
        uint4 v = make_uint4(0u, 0u, 0u, 0u);
        int grow = row0 + row;
        if (grow < n) v = *(const uint4*)(X16 + (size_t)grow * D + k8 * 8);
        *(uint4*)(As + row * LDP + k8 * 8) = v;
        uint4 wv = *(const uint4*)(W16 + row * D + k8 * 8);
        *(uint4*)(Ws + row * LDP + k8 * 8) = wv;
    }
    __syncthreads();

    int warp = tid >> 5;
    wmma::fragment<wmma::accumulator, 16, 16, 16, float> cfrag[8];
    for (int j = 0; j < 8; j++) wmma::fill_fragment(cfrag[j], 0.0f);

    for (int k = 0; k < 8; k++) {
        wmma::fragment<wmma::matrix_a, 16, 16, 16, __half, wmma::row_major> afrag;
        wmma::load_matrix_sync(afrag, As + (warp * 16) * LDP + k * 16, LDP);
        for (int j = 0; j < 8; j++) {
            wmma::fragment<wmma::matrix_b, 16, 16, 16, __half, wmma::col_major> bfrag;
            wmma::load_matrix_sync(bfrag, Ws + (j * 16) * LDP + k * 16, LDP);
            wmma::mma_sync(cfrag[j], afrag, bfrag, cfrag[j]);
        }
    }
    __syncthreads();   // tiles dead; reuse smem for the fp32 C buffer

    float* Cs = (float*)smbuf;           // [128][128]
    for (int j = 0; j < 8; j++)
        wmma::store_matrix_sync(Cs + (warp * 16) * 128 + j * 16, cfrag[j], 128,
                                wmma::mem_row_major);
    __syncthreads();

    // epilogue: thread t handles row t/2, 64 channels; pair-reduce projections
    int row = tid >> 1;
    int hh = tid & 1;
    int c0 = hh * 64;
    int grow = row0 + row;
    float p1 = 0.f, p2 = 0.f;
    __half2 hv[32];
    for (int j = 0; j < 32; j++) {
        float ox = Cs[row * 128 + c0 + 2 * j]     + bias[c0 + 2 * j];
        float oy = Cs[row * 128 + c0 + 2 * j + 1] + bias[c0 + 2 * j + 1];
        p1 += ox * aW[c0 + 2 * j]     + oy * aW[c0 + 2 * j + 1];
        p2 += ox * aW[D + c0 + 2 * j] + oy * aW[D + c0 + 2 * j + 1];
        hv[j] = __floats2half2_rn(ox, oy);
    }
    p1 += __shfl_xor_sync(0xffffffffu, p1, 1);
    p2 += __shfl_xor_sync(0xffffffffu, p2, 1);
    if (grow < n) {
        uint4* dst4 = (uint4*)(Z16 + (size_t)grow * D + c0);
        const uint4* src4 = (const uint4*)hv;
        for (int j = 0; j < 8; j++) dst4[j] = src4[j];
        if (hh == 0) { asrc[grow] = p1; adst[grow] = p2; }
    }
}

// ---------------- fused segment softmax + weighted gather ------------------
// One warp per dst node. Fast path (deg <= 128, ~all nodes at mean deg 32):
// pass 1 stages (e, src) per edge into per-warp smem; pass 2a converts e ->
// alpha in place; pass 2b reads alpha/src from smem (no shfl chains, no
// second csr/asrc gather) and issues independent LDG.128 row loads, 2 edges
// per step, 16 lanes x 16B per row. Slow path recomputes (rare).
// outh != 0: write relu'd fp16; else fp32 to outf.
#define AGG_CAP 128

__global__ __launch_bounds__(256) void aggregate_kernel(
    const __half* __restrict__ z16,
    const float* __restrict__ asrc,
    const float* __restrict__ adst,
    const int* __restrict__ off,
    const int* __restrict__ csr_src,
    const float* __restrict__ ab,
    float* __restrict__ outf,
    __half* __restrict__ outh, int n)
{
    __shared__ float s_alpha[8][AGG_CAP + 2];
    __shared__ int   s_sj[8][AGG_CAP + 2];

    int node = (blockIdx.x * blockDim.x + threadIdx.x) >> 5;
    int lane = threadIdx.x & 31;
    int w = (threadIdx.x >> 5);
    if (node >= n) return;
    int beg = off[node], end = off[node + 1];
    int deg = end - beg;
    float advv = adst[node] + ab[0];

    int hf = lane >> 4;
    int chan = (lane & 15) * 8;
    float acc8[8] = {0.f, 0.f, 0.f, 0.f, 0.f, 0.f, 0.f, 0.f};
    float m = -1e30f, s = 0.f;

    if (deg <= AGG_CAP) {
        // ---- pass 1: gather e/src, stage to smem, online stats ----
        for (int idx = lane; idx < deg; idx += 32) {
            int sj = csr_src[beg + idx];
            float e = asrc[sj] + advv;
            e = (e > 0.f) ? e : 0.01f * e;
            s_alpha[w][idx] = e;
            s_sj[w][idx] = sj;
            if (e > m) { s = s * __expf(m - e) + 1.f; m = e; }
            else       { s += __expf(e - m); }
        }
#pragma unroll
        for (int o = 16; o; o >>= 1) {
            float m2 = __shfl_xor_sync(0xffffffffu, m, o);
            float s2 = __shfl_xor_sync(0xffffffffu, s, o);
            float mn = fmaxf(m, m2);
            s = s * __expf(m - mn) + s2 * __expf(m2 - mn);
            m = mn;
        }
        float inv_s = (deg > 0) ? 1.f / s : 0.f;
        // ---- pass 2a: e -> alpha in smem; pad one slot ----
        for (int idx = lane; idx < deg; idx += 32) {
            s_alpha[w][idx] = __expf(s_alpha[w][idx] - m) * inv_s;
        }
        if (lane == 0) { s_alpha[w][deg] = 0.f; s_sj[w][deg] = 0; }
        __syncwarp();
        // ---- pass 2b: weighted gather, 2 edges/step ----
        int steps = (deg + 1) >> 1;
#pragma unroll 8
        for (int t = 0; t < steps; t++) {
            int idx = 2 * t + hf;
            float a  = s_alpha[w][idx];
            int   sn = s_sj[w][idx];
            uint4 raw = *(const uint4*)(z16 + (size_t)sn * D + chan);
            __half2 q0 = *reinterpret_cast<__half2*>(&raw.x);
            __half2 q1 = *reinterpret_cast<__half2*>(&raw.y);
            __half2 q2 = *reinterpret_cast<__half2*>(&raw.z);
            __half2 q3 = *reinterpret_cast<__half2*>(&raw.w);
            float2 f0 = __half22float2(q0);
            float2 f1 = __half22float2(q1);
            float2 f2 = __half22float2(q2);
            float2 f3 = __half22float2(q3);
            acc8[0] += a * f0.x;
            acc8[1] += a * f0.y;
            acc8[2] += a * f1.x;
            acc8[3] += a * f1.y;
            acc8[4] += a * f2.x;
            acc8[5] += a * f2.y;
            acc8[6] += a * f3.x;
            acc8[7] += a * f3.y;
        }
    } else {
        // ---- slow path (deg > 128): recompute ----
        for (int j = beg + lane; j < end; j += 32) {
            float e = asrc[csr_src[j]] + advv;
            e = (e > 0.f) ? e : 0.01f * e;
            if (e > m) { s = s * __expf(m - e) + 1.f; m = e; }
            else       { s += __expf(e - m); }
        }
#pragma unroll
        for (int o = 16; o; o >>= 1) {
            float m2 = __shfl_xor_sync(0xffffffffu, m, o);
            float s2 = __shfl_xor_sync(0xffffffffu, s, o);
            float mn = fmaxf(m, m2);
            s = s * __expf(m - mn) + s2 * __expf(m2 - mn);
            m = mn;
        }
        float inv_s = 1.f / s;
        for (int j0 = beg; j0 < end; j0 += 32) {
            int j = j0 + lane;
            float alpha = 0.f;
            int sj = 0;
            if (j < end) {
                sj = csr_src[j];
                float e = asrc[sj] + advv;
                e = (e > 0.f) ? e : 0.01f * e;
                alpha = __expf(e - m) * inv_s;
            }
            int cnt = min(32, end - j0);
            int steps = (cnt + 1) >> 1;
            for (int t = 0; t < steps; t++) {
                float a  = __shfl_sync(0xffffffffu, alpha, 2 * t + hf);
                int   sn = __shfl_sync(0xffffffffu, sj,    2 * t + hf);
                uint4 raw = *(const uint4*)(z16 + (size_t)sn * D + chan);
                __half2 q0 = *reinterpret_cast<__half2*>(&raw.x);
                __half2 q1 = *reinterpret_cast<__half2*>(&raw.y);
                __half2 q2 = *reinterpret_cast<__half2*>(&raw.z);
                __half2 q3 = *reinterpret_cast<__half2*>(&raw.w);
                float2 f0 = __half22float2(q0);
                float2 f1 = __half22float2(q1);
                float2 f2 = __half22float2(q2);
                float2 f3 = __half22float2(q3);
                acc8[0] += a * f0.x;
                acc8[1] += a * f0.y;
                acc8[2] += a * f1.x;
                acc8[3] += a * f1.y;
                acc8[4] += a * f2.x;
                acc8[5] += a * f2.y;
                acc8[6] += a * f3.x;
                acc8[7] += a * f3.y;
            }
        }
    }

    // combine the two edge-halves
#pragma unroll
    for (int c = 0; c < 8; c++) {
        acc8[c] += __shfl_xor_sync(0xffffffffu, acc8[c], 16);
    }

    if (lane < 16) {
        if (outh != 0) {
            __half2 h0 = __floats2half2_rn(fmaxf(acc8[0], 0.f), fmaxf(acc8[1], 0.f));
            __half2 h1 = __floats2half2_rn(fmaxf(acc8[2], 0.f), fmaxf(acc8[3], 0.f));
            __half2 h2 = __floats2half2_rn(fmaxf(acc8[4], 0.f), fmaxf(acc8[5], 0.f));
            __half2 h3 = __floats2half2_rn(fmaxf(acc8[6], 0.f), fmaxf(acc8[7], 0.f));
            uint4 u;
            u.x = *reinterpret_cast<unsigned*>(&h0);
            u.y = *reinterpret_cast<unsigned*>(&h1);
            u.z = *reinterpret_cast<unsigned*>(&h2);
            u.w = *reinterpret_cast<unsigned*>(&h3);
            *(uint4*)(outh + (size_t)node * D + chan) = u;
        } else {
            *(float4*)(outf + (size_t)node * D + chan) =
                make_float4(acc8[0], acc8[1], acc8[2], acc8[3]);
            *(float4*)(outf + (size_t)node * D + chan + 4) =
                make_float4(acc8[4], acc8[5], acc8[6], acc8[7]);
        }
    }
}

// ---------------- launch ----------------------------------------------------
extern "C" void kernel_launch(void* const* d_in, const int* in_sizes, int n_in,
                              void* d_out, int out_size)
{
    const float* x   = (const float*)d_in[0];
    const int*   src = (const int*)d_in[1];
    const int*   dst = (const int*)d_in[2];
    // d_in[3] = t (unused)
    const float* W0  = (const float*)d_in[4];
    const float* b0  = (const float*)d_in[5];
    const float* aW0 = (const float*)d_in[6];
    const float* ab0 = (const float*)d_in[7];
    const float* W1  = (const float*)d_in[8];
    const float* b1  = (const float*)d_in[9];
    const float* aW1 = (const float*)d_in[10];
    const float* ab1 = (const float*)d_in[11];
    const float* W2  = (const float*)d_in[12];
    const float* b2  = (const float*)d_in[13];
    const float* aW2 = (const float*)d_in[14];
    const float* ab2 = (const float*)d_in[15];

    int n = in_sizes[0] / D;   // 50000
    int E = in_sizes[1];       // 1600000

    __half *x16, *z16, *w16;
    float *asrc, *adst;
    int *deg, *cur, *off, *csr, *bsum;
    cudaGetSymbolAddress((void**)&x16,  g_x16);
    cudaGetSymbolAddress((void**)&z16,  g_z16);
    cudaGetSymbolAddress((void**)&w16,  g_w16);
    cudaGetSymbolAddress((void**)&asrc, g_asrc);
    cudaGetSymbolAddress((void**)&adst, g_adst);
    cudaGetSymbolAddress((void**)&deg,  g_deg);
    cudaGetSymbolAddress((void**)&cur,  g_cur);
    cudaGetSymbolAddress((void**)&off,  g_off);
    cudaGetSymbolAddress((void**)&bsum, g_bsum);
    cudaGetSymbolAddress((void**)&csr,  g_csr_src);

    float* outf = (float*)d_out;

    // idempotent, host-side, not a stream op (safe under graph capture)
    cudaFuncSetAttribute(gemm_kernel, cudaFuncAttributeMaxDynamicSharedMemorySize,
                         GEMM_SMEM_BYTES);

    int tb = 256;
    int scan_blocks = (n + SCAN_TPB - 1) / SCAN_TPB;   // 49
    // ---- CSR build ----
    zero_kernel<<<(n + tb - 1) / tb, tb>>>(deg, cur, n);
    hist_kernel<<<(E / 4 + tb - 1) / tb, tb>>>(dst, deg, E);
    scan_bsum_kernel<<<scan_blocks, SCAN_TPB>>>(deg, bsum, n);
    scan_bpre_kernel<<<1, 64>>>(bsum, off, scan_blocks, n);
    scan_write_kernel<<<scan_blocks, SCAN_TPB>>>(deg, bsum, off, n);
    scatter_kernel<<<(E + tb - 1) / tb, tb>>>(src, dst, off, cur, csr, E);

    // ---- conversions: x and the three weight matrices to fp16 ----
    int n8x = n * D / 8;
    cvt_x_kernel<<<(n8x + tb - 1) / tb, tb>>>(x, x16, n8x);
    cvt_w_kernel<<<(3 * 2048 + tb - 1) / tb, tb>>>(W0, W1, W2, w16);

    int gemm_blocks = (n + 127) / 128;
    int warp_blocks = (n + 7) / 8;

    // ---- layer 0 (fp16 relu out -> x16) ----
    gemm_kernel<<<gemm_blocks, tb, GEMM_SMEM_BYTES>>>(x16, w16, b0, aW0, z16, asrc, adst, n);
    aggregate_kernel<<<warp_blocks, tb>>>(z16, asrc, adst, off, csr, ab0, 0, x16, n);
    // ---- layer 1 ----
    gemm_kernel<<<gemm_blocks, tb, GEMM_SMEM_BYTES>>>(x16, w16 + D * D, b1, aW1, z16, asrc, adst, n);
    aggregate_kernel<<<warp_blocks, tb>>>(z16, asrc, adst, off, csr, ab1, 0, x16, n);
    // ---- layer 2 (fp32 out -> d_out) ----
    gemm_kernel<<<gemm_blocks, tb, GEMM_SMEM_BYTES>>>(x16, w16 + 2 * D * D, b2, aW2, z16, asrc, adst, n);
    aggregate_kernel<<<warp_blocks, tb>>>(z16, asrc, adst, off, csr, ab2, outf, 0, n);
}

// round 17
// speedup vs baseline: 1.0840x; 1.0067x over previous
#include <cuda_runtime.h>
#include <cuda_fp16.h>
#include <mma.h>

using namespace nvcuda;

// Problem constants (fixed by the dataset)
#define N_NODES 50000
#define N_EDGES 1600000
#define D 128

// ---------------- scratch (device globals; no allocation allowed) ----------
__device__ __align__(16) __half g_x16[N_NODES * D];  // fp16 GEMM input
__device__ __align__(16) __half g_z16[N_NODES * D];  // fp16 GEMM output / gather payload
__device__ __align__(16) __half g_w16[3 * D * D];    // fp16 weights
__device__ float g_asrc[N_NODES];
__device__ float g_adst[N_NODES];
__device__ int   g_deg[N_NODES];
__device__ int   g_cur[N_NODES];
__device__ int   g_off[N_NODES + 1];
__device__ int   g_bsum[64];            // per-block sums for the 2-phase scan
__device__ int   g_csr_src[N_EDGES];

// ---------------- CSR build ------------------------------------------------
__global__ void hist_kernel(const int* __restrict__ dst, int* __restrict__ deg, int E) {
    int i4 = (blockIdx.x * blockDim.x + threadIdx.x) * 4;
    if (i4 + 3 < E) {
        int4 v = *(const int4*)(dst + i4);
        atomicAdd(&deg[v.x], 1);
        atomicAdd(&deg[v.y], 1);
        atomicAdd(&deg[v.z], 1);
        atomicAdd(&deg[v.w], 1);
    } else {
        for (int i = i4; i < E; i++) atomicAdd(&deg[dst[i]], 1);
    }
}

// ---- 2-phase coalesced exclusive scan (1024 elems per block) ----
#define SCAN_TPB 1024

// phase A: per-block reduce (coalesced)
__global__ void scan_bsum_kernel(const int* __restrict__ deg, int* __restrict__ bsum,
                                 int n) {
    __shared__ int wsum[32];
    int lane = threadIdx.x & 31, wid = threadIdx.x >> 5;
    int i = blockIdx.x * SCAN_TPB + threadIdx.x;
    int x = (i < n) ? deg[i] : 0;
#pragma unroll
    for (int o = 16; o; o >>= 1) x += __shfl_xor_sync(0xffffffffu, x, o);
    if (lane == 0) wsum[wid] = x;
    __syncthreads();
    if (wid == 0) {
        int w = wsum[lane];
#pragma unroll
        for (int o = 16; o; o >>= 1) w += __shfl_xor_sync(0xffffffffu, w, o);
        if (lane == 0) bsum[blockIdx.x] = w;
    }
}

// phase B: per-block exclusive scan; warp 0 reduces its own block-prefix from
// bsum (t < blockIdx), last block writes off[n]=total. Coalesced off store.
__global__ void scan_write_kernel(const int* __restrict__ deg, const int* __restrict__ bsum,
                                  int* __restrict__ off, int n, int nb) {
    __shared__ int wsum[32];
    __shared__ int s_bpre;
    int lane = threadIdx.x & 31, wid = threadIdx.x >> 5;
    int i = blockIdx.x * SCAN_TPB + threadIdx.x;
    int v = (i < n) ? deg[i] : 0;
    int x = v;
#pragma unroll
    for (int o = 1; o < 32; o <<= 1) {
        int y = __shfl_up_sync(0xffffffffu, x, o);
        if (lane >= o) x += y;
    }
    if (lane == 31) wsum[wid] = x;
    // warp 0: block prefix = sum of bsum[t] for t < blockIdx (nb <= 64)
    if (wid == 0) {
        int bid = blockIdx.x;
        int l2 = lane + 32;
        int p = ((lane < nb && lane < bid) ? bsum[lane] : 0)
              + ((l2 < nb && l2 < bid) ? bsum[l2] : 0);
#pragma unroll
        for (int o = 16; o; o >>= 1) p += __shfl_xor_sync(0xffffffffu, p, o);
        if (lane == 0) {
            s_bpre = p;
            if (bid == nb - 1) off[n] = p + bsum[nb - 1];
        }
    }
    __syncthreads();
    if (wid == 0) {
        int w = wsum[lane];
#pragma unroll
        for (int o = 1; o < 32; o <<= 1) {
            int y = __shfl_up_sync(0xffffffffu, w, o);
            if (lane >= o) w += y;
        }
        wsum[lane] = w;
    }
    __syncthreads();
    int excl = x - v + (wid ? wsum[wid - 1] : 0) + s_bpre;
    if (i < n) off[i] = excl;
}

__global__ void scatter_kernel(const int* __restrict__ src, const int* __restrict__ dst,
                               const int* __restrict__ off, int* __restrict__ cur,
                               int* __restrict__ csr_src, int E) {
    int i = blockIdx.x * blockDim.x + threadIdx.x;
    if (i >= E) return;
    int d = dst[i];
    int p = off[d] + atomicAdd(&cur[d], 1);
    csr_src[p] = src[i];
}

// ---------------- fp32 -> fp16 conversion (x + all 3 weights, one launch) ---
__global__ void cvt_all_kernel(const float* __restrict__ x,
                               const float* __restrict__ W0, const float* __restrict__ W1,
                               const float* __restrict__ W2,
                               __half* __restrict__ x16, __half* __restrict__ w16,
                               int n8x) {
    int i = blockIdx.x * blockDim.x + threadIdx.x;
    int total = n8x + 3 * 2048;
    if (i >= total) return;
    const float4* p;
    uint4* dstp;
    if (i < n8x) {
        p = (const float4*)x + (size_t)i * 2;
        dstp = (uint4*)x16 + i;
    } else {
        int j = i - n8x;
        int which = j >> 11, jj = j & 2047;
        const float* W = (which == 0) ? W0 : ((which == 1) ? W1 : W2);
        p = (const float4*)W + (size_t)jj * 2;
        dstp = (uint4*)(w16 + (size_t)which * D * D) + jj;
    }
    float4 a = p[0], b = p[1];
    __half2 h0 = __floats2half2_rn(a.x, a.y);
    __half2 h1 = __floats2half2_rn(a.z, a.w);
    __half2 h2 = __floats2half2_rn(b.x, b.y);
    __half2 h3 = __floats2half2_rn(b.z, b.w);
    uint4 u;
    u.x = *reinterpret_cast<unsigned*>(&h0);
    u.y = *reinterpret_cast<unsigned*>(&h1);
    u.z = *reinterpret_cast<unsigned*>(&h2);
    u.w = *reinterpret_cast<unsigned*>(&h3);
    *dstp = u;
}

// ---------------- WMMA GEMM + fused attention projections -------------------
// Z16 = fp16(X16 @ W16^T + b); asrc/adst = Z @ aW halves from fp32 accums.
// Block: 128 rows, full N=128, full K=128 staged once. 8 warps, 16 rows each,
// 8 accumulator fragments per warp. Padded ld=136 halves for staging tiles.
// W is [n][k] row-major; as a col_major wmma matrix_b this gives
// B(k,n) = W[n][k] exactly.
#define LDP 136
#define GEMM_SMEM_BYTES (2 * 128 * LDP * 2)   // 69632; also covers 128*128*4 float C

__global__ __launch_bounds__(256) void gemm_kernel(
    const __half* __restrict__ X16, const __half* __restrict__ W16,
    const float* __restrict__ bias, const float* __restrict__ aW,
    __half* __restrict__ Z16, float* __restrict__ asrc, float* __restrict__ adst, int n)
{
    extern __shared__ __half smbuf[];
    __half* As = smbuf;                  // [128][LDP]
    __half* Ws = smbuf + 128 * LDP;      // [128][LDP]
    int tid = threadIdx.x;
    int row0 = blockIdx.x * 128;

    // stage X tile (zero-filled past n) and W, 8 x 16B chunks per thread each
    for (int i = 0; i < 8; i++) {
        int c = tid + i * 256;           // 0..2047
        int row = c >> 4;
        int k8 = c & 15;
        uint4 v = make_uint4(0u, 0u, 0u, 0u);
        int grow = row0 + row;
        if (grow < n) v = *(const uint4*)(X16 + (size_t)grow * D + k8 * 8);
        *(uint4*)(As + row * LDP + k8 * 8) = v;
        uint4 wv = *(const uint4*)(W16 + row * D + k8 * 8);
        *(uint4*)(Ws + row * LDP + k8 * 8) = wv;
    }
    __syncthreads();

    int warp = tid >> 5;
    wmma::fragment<wmma::accumulator, 16, 16, 16, float> cfrag[8];
    for (int j = 0; j < 8; j++) wmma::fill_fragment(cfrag[j], 0.0f);

    for (int k = 0; k < 8; k++) {
        wmma::fragment<wmma::matrix_a, 16, 16, 16, __half, wmma::row_major> afrag;
        wmma::load_matrix_sync(afrag, As + (warp * 16) * LDP + k * 16, LDP);
        for (int j = 0; j < 8; j++) {
            wmma::fragment<wmma::matrix_b, 16, 16, 16, __half, wmma::col_major> bfrag;
            wmma::load_matrix_sync(bfrag, Ws + (j * 16) * LDP + k * 16, LDP);
            wmma::mma_sync(cfrag[j], afrag, bfrag, cfrag[j]);
        }
    }
    __syncthreads();   // tiles dead; reuse smem for the fp32 C buffer

    float* Cs = (float*)smbuf;           // [128][128]
    for (int j = 0; j < 8; j++)
        wmma::store_matrix_sync(Cs + (warp * 16) * 128 + j * 16, cfrag[j], 128,
                                wmma::mem_row_major);
    __syncthreads();

    // epilogue: thread t handles row t/2, 64 channels; pair-reduce projections
    int row = tid >> 1;
    int hh = tid & 1;
    int c0 = hh * 64;
    int grow = row0 + row;
    float p1 = 0.f, p2 = 0.f;
    __half2 hv[32];
    for (int j = 0; j < 32; j++) {
        float ox = Cs[row * 128 + c0 + 2 * j]     + bias[c0 + 2 * j];
        float oy = Cs[row * 128 + c0 + 2 * j + 1] + bias[c0 + 2 * j + 1];
        p1 += ox * aW[c0 + 2 * j]     + oy * aW[c0 + 2 * j + 1];
        p2 += ox * aW[D + c0 + 2 * j] + oy * aW[D + c0 + 2 * j + 1];
        hv[j] = __floats2half2_rn(ox, oy);
    }
    p1 += __shfl_xor_sync(0xffffffffu, p1, 1);
    p2 += __shfl_xor_sync(0xffffffffu, p2, 1);
    if (grow < n) {
        uint4* dst4 = (uint4*)(Z16 + (size_t)grow * D + c0);
        const uint4* src4 = (const uint4*)hv;
        for (int j = 0; j < 8; j++) dst4[j] = src4[j];
        if (hh == 0) { asrc[grow] = p1; adst[grow] = p2; }
    }
}

// ---------------- fused segment softmax + weighted gather ------------------
// One warp per dst node. Fast path (deg <= 128, ~all nodes at mean deg 32):
// pass 1 stages (e, src) per edge into per-warp smem; pass 2a converts e ->
// alpha in place; pass 2b reads alpha/src from smem (no shfl chains, no
// second csr/asrc gather) and issues independent LDG.128 row loads, 2 edges
// per step, 16 lanes x 16B per row. Slow path recomputes (rare).
// outh != 0: write relu'd fp16; else fp32 to outf.
#define AGG_CAP 128

__global__ __launch_bounds__(256) void aggregate_kernel(
    const __half* __restrict__ z16,
    const float* __restrict__ asrc,
    const float* __restrict__ adst,
    const int* __restrict__ off,
    const int* __restrict__ csr_src,
    const float* __restrict__ ab,
    float* __restrict__ outf,
    __half* __restrict__ outh, int n)
{
    __shared__ float s_alpha[8][AGG_CAP + 2];
    __shared__ int   s_sj[8][AGG_CAP + 2];

    int node = (blockIdx.x * blockDim.x + threadIdx.x) >> 5;
    int lane = threadIdx.x & 31;
    int w = (threadIdx.x >> 5);
    if (node >= n) return;
    int beg = off[node], end = off[node + 1];
    int deg = end - beg;
    float advv = adst[node] + ab[0];

    int hf = lane >> 4;
    int chan = (lane & 15) * 8;
    float acc8[8] = {0.f, 0.f, 0.f, 0.f, 0.f, 0.f, 0.f, 0.f};
    float m = -1e30f, s = 0.f;

    if (deg <= AGG_CAP) {
        // ---- pass 1: gather e/src, stage to smem, online stats ----
        for (int idx = lane; idx < deg; idx += 32) {
            int sj = csr_src[beg + idx];
            float e = asrc[sj] + advv;
            e = (e > 0.f) ? e : 0.01f * e;
            s_alpha[w][idx] = e;
            s_sj[w][idx] = sj;
            if (e > m) { s = s * __expf(m - e) + 1.f; m = e; }
            else       { s += __expf(e - m); }
        }
#pragma unroll
        for (int o = 16; o; o >>= 1) {
            float m2 = __shfl_xor_sync(0xffffffffu, m, o);
            float s2 = __shfl_xor_sync(0xffffffffu, s, o);
            float mn = fmaxf(m, m2);
            s = s * __expf(m - mn) + s2 * __expf(m2 - mn);
            m = mn;
        }
        float inv_s = (deg > 0) ? 1.f / s : 0.f;
        // ---- pass 2a: e -> alpha in smem; pad one slot ----
        for (int idx = lane; idx < deg; idx += 32) {
            s_alpha[w][idx] = __expf(s_alpha[w][idx] - m) * inv_s;
        }
        if (lane == 0) { s_alpha[w][deg] = 0.f; s_sj[w][deg] = 0; }
        __syncwarp();
        // ---- pass 2b: weighted gather, 2 edges/step ----
        int steps = (deg + 1) >> 1;
#pragma unroll 8
        for (int t = 0; t < steps; t++) {
            int idx = 2 * t + hf;
            float a  = s_alpha[w][idx];
            int   sn = s_sj[w][idx];
            uint4 raw = *(const uint4*)(z16 + (size_t)sn * D + chan);
            __half2 q0 = *reinterpret_cast<__half2*>(&raw.x);
            __half2 q1 = *reinterpret_cast<__half2*>(&raw.y);
            __half2 q2 = *reinterpret_cast<__half2*>(&raw.z);
            __half2 q3 = *reinterpret_cast<__half2*>(&raw.w);
            float2 f0 = __half22float2(q0);
            float2 f1 = __half22float2(q1);
            float2 f2 = __half22float2(q2);
            float2 f3 = __half22float2(q3);
            acc8[0] += a * f0.x;
            acc8[1] += a * f0.y;
            acc8[2] += a * f1.x;
            acc8[3] += a * f1.y;
            acc8[4] += a * f2.x;
            acc8[5] += a * f2.y;
            acc8[6] += a * f3.x;
            acc8[7] += a * f3.y;
        }
    } else {
        // ---- slow path (deg > 128): recompute ----
        for (int j = beg + lane; j < end; j += 32) {
            float e = asrc[csr_src[j]] + advv;
            e = (e > 0.f) ? e : 0.01f * e;
            if (e > m) { s = s * __expf(m - e) + 1.f; m = e; }
            else       { s += __expf(e - m); }
        }
#pragma unroll
        for (int o = 16; o; o >>= 1) {
            float m2 = __shfl_xor_sync(0xffffffffu, m, o);
            float s2 = __shfl_xor_sync(0xffffffffu, s, o);
            float mn = fmaxf(m, m2);
            s = s * __expf(m - mn) + s2 * __expf(m2 - mn);
            m = mn;
        }
        float inv_s = 1.f / s;
        for (int j0 = beg; j0 < end; j0 += 32) {
            int j = j0 + lane;
            float alpha = 0.f;
            int sj = 0;
            if (j < end) {
                sj = csr_src[j];
                float e = asrc[sj] + advv;
                e = (e > 0.f) ? e : 0.01f * e;
                alpha = __expf(e - m) * inv_s;
            }
            int cnt = min(32, end - j0);
            int steps = (cnt + 1) >> 1;
            for (int t = 0; t < steps; t++) {
                float a  = __shfl_sync(0xffffffffu, alpha, 2 * t + hf);
                int   sn = __shfl_sync(0xffffffffu, sj,    2 * t + hf);
                uint4 raw = *(const uint4*)(z16 + (size_t)sn * D + chan);
                __half2 q0 = *reinterpret_cast<__half2*>(&raw.x);
                __half2 q1 = *reinterpret_cast<__half2*>(&raw.y);
                __half2 q2 = *reinterpret_cast<__half2*>(&raw.z);
                __half2 q3 = *reinterpret_cast<__half2*>(&raw.w);
                float2 f0 = __half22float2(q0);
                float2 f1 = __half22float2(q1);
                float2 f2 = __half22float2(q2);
                float2 f3 = __half22float2(q3);
                acc8[0] += a * f0.x;
                acc8[1] += a * f0.y;
                acc8[2] += a * f1.x;
                acc8[3] += a * f1.y;
                acc8[4] += a * f2.x;
                acc8[5] += a * f2.y;
                acc8[6] += a * f3.x;
                acc8[7] += a * f3.y;
            }
        }
    }

    // combine the two edge-halves
#pragma unroll
    for (int c = 0; c < 8; c++) {
        acc8[c] += __shfl_xor_sync(0xffffffffu, acc8[c], 16);
    }

    if (lane < 16) {
        if (outh != 0) {
            __half2 h0 = __floats2half2_rn(fmaxf(acc8[0], 0.f), fmaxf(acc8[1], 0.f));
            __half2 h1 = __floats2half2_rn(fmaxf(acc8[2], 0.f), fmaxf(acc8[3], 0.f));
            __half2 h2 = __floats2half2_rn(fmaxf(acc8[4], 0.f), fmaxf(acc8[5], 0.f));
            __half2 h3 = __floats2half2_rn(fmaxf(acc8[6], 0.f), fmaxf(acc8[7], 0.f));
            uint4 u;
            u.x = *reinterpret_cast<unsigned*>(&h0);
            u.y = *reinterpret_cast<unsigned*>(&h1);
            u.z = *reinterpret_cast<unsigned*>(&h2);
            u.w = *reinterpret_cast<unsigned*>(&h3);
            *(uint4*)(outh + (size_t)node * D + chan) = u;
        } else {
            *(float4*)(outf + (size_t)node * D + chan) =
                make_float4(acc8[0], acc8[1], acc8[2], acc8[3]);
            *(float4*)(outf + (size_t)node * D + chan + 4) =
                make_float4(acc8[4], acc8[5], acc8[6], acc8[7]);
        }
    }
}

// ---------------- launch ----------------------------------------------------
extern "C" void kernel_launch(void* const* d_in, const int* in_sizes, int n_in,
                              void* d_out, int out_size)
{
    const float* x   = (const float*)d_in[0];
    const int*   src = (const int*)d_in[1];
    const int*   dst = (const int*)d_in[2];
    // d_in[3] = t (unused)
    const float* W0  = (const float*)d_in[4];
    const float* b0  = (const float*)d_in[5];
    const float* aW0 = (const float*)d_in[6];
    const float* ab0 = (const float*)d_in[7];
    const float* W1  = (const float*)d_in[8];
    const float* b1  = (const float*)d_in[9];
    const float* aW1 = (const float*)d_in[10];
    const float* ab1 = (const float*)d_in[11];
    const float* W2  = (const float*)d_in[12];
    const float* b2  = (const float*)d_in[13];
    const float* aW2 = (const float*)d_in[14];
    const float* ab2 = (const float*)d_in[15];

    int n = in_sizes[0] / D;   // 50000
    int E = in_sizes[1];       // 1600000

    __half *x16, *z16, *w16;
    float *asrc, *adst;
    int *deg, *cur, *off, *csr, *bsum;
    cudaGetSymbolAddress((void**)&x16,  g_x16);
    cudaGetSymbolAddress((void**)&z16,  g_z16);
    cudaGetSymbolAddress((void**)&w16,  g_w16);
    cudaGetSymbolAddress((void**)&asrc, g_asrc);
    cudaGetSymbolAddress((void**)&adst, g_adst);
    cudaGetSymbolAddress((void**)&deg,  g_deg);
    cudaGetSymbolAddress((void**)&cur,  g_cur);
    cudaGetSymbolAddress((void**)&off,  g_off);
    cudaGetSymbolAddress((void**)&bsum, g_bsum);
    cudaGetSymbolAddress((void**)&csr,  g_csr_src);

    float* outf = (float*)d_out;

    // idempotent, host-side, not a stream op (safe under graph capture)
    cudaFuncSetAttribute(gemm_kernel, cudaFuncAttributeMaxDynamicSharedMemorySize,
                         GEMM_SMEM_BYTES);

    int tb = 256;
    int scan_blocks = (n + SCAN_TPB - 1) / SCAN_TPB;   // 49
    // ---- CSR build ----
    cudaMemsetAsync(deg, 0, (size_t)n * sizeof(int), 0);
    cudaMemsetAsync(cur, 0, (size_t)n * sizeof(int), 0);
    hist_kernel<<<(E / 4 + tb - 1) / tb, tb>>>(dst, deg, E);
    scan_bsum_kernel<<<scan_blocks, SCAN_TPB>>>(deg, bsum, n);
    scan_write_kernel<<<scan_blocks, SCAN_TPB>>>(deg, bsum, off, n, scan_blocks);
    scatter_kernel<<<(E + tb - 1) / tb, tb>>>(src, dst, off, cur, csr, E);

    // ---- conversions: x and the three weight matrices, one launch ----
    int n8x = n * D / 8;
    cvt_all_kernel<<<(n8x + 3 * 2048 + tb - 1) / tb, tb>>>(x, W0, W1, W2, x16, w16, n8x);

    int gemm_blocks = (n + 127) / 128;
    int warp_blocks = (n + 7) / 8;

    // ---- layer 0 (fp16 relu out -> x16) ----
    gemm_kernel<<<gemm_blocks, tb, GEMM_SMEM_BYTES>>>(x16, w16, b0, aW0, z16, asrc, adst, n);
    aggregate_kernel<<<warp_blocks, tb>>>(z16, asrc, adst, off, csr, ab0, 0, x16, n);
    // ---- layer 1 ----
    gemm_kernel<<<gemm_blocks, tb, GEMM_SMEM_BYTES>>>(x16, w16 + D * D, b1, aW1, z16, asrc, adst, n);
    aggregate_kernel<<<warp_blocks, tb>>>(z16, asrc, adst, off, csr, ab1, 0, x16, n);
    // ---- layer 2 (fp32 out -> d_out) ----
    gemm_kernel<<<gemm_blocks, tb, GEMM_SMEM_BYTES>>>(x16, w16 + 2 * D * D, b2, aW2, z16, asrc, adst, n);
    aggregate_kernel<<<warp_blocks, tb>>>(z16, asrc, adst, off, csr, ab2, outf, 0, n);
}